// round 13
// baseline (speedup 1.0000x reference)
#include <cuda_runtime.h>
#include <cuda_fp16.h>
#include <math.h>
#include <stdint.h>

#define T_STEPS 2048
#define ISZ 256
#define HSZ 512
#define BSZ 64
#define NB 128
#define TPB 256
#define BN_EPS 1e-5f

// ---- SMEM layout (bytes) ----
// pre-phase:
#define SM_PW 0          // 128 rows x 260 floats = 133120 B
#define SM_PX 133120     // 256 rows x 72 floats  = 73728 B  -> end 206848
// recurrent phase (overlaps pre-phase region; separated by grid barrier):
#define SM_H      0      // 64 cols x 520 halves (260 words) = 66560 B
#define SM_WP     66560  // permuted W fragments: 4096 words = 16384 B -> 82944
#define SM_SPILL  82944  // 16 rows x 68 floats = 4352 B -> 87296
#define SM_BNB    87296  // 16 x 64 floats = 4096 B -> 91392
// params:
#define SM_PAR    206848
#define SMEM_BYTES 207872

#define SPILL_STR 68
#define HSTR_W 260        // H row stride in 32-bit words (520 halves)

struct Par {
    float sca[16], shf[16];
    float gh[16], bh[16];
    float gc[4], bc[4];
    float csum[8], csq[8];
};

// ---- device globals (static, no allocation) ----
__device__ __half g_h16[2][BSZ * HSZ];       // h fp16, batch-major [col][hidden]
__device__ float g_bnb[268435456];           // [t][2048 rows][64]: BN(Wih@x)+bias
__device__ unsigned long long g_slot[NB];    // per-block arrival slots
__device__ unsigned long long g_release = 0ULL;

// ---- helpers ----
__device__ __forceinline__ void cp_async16(void* smem_dst, const void* gsrc) {
    unsigned s;
    asm("{ .reg .u64 t; cvta.to.shared.u64 t, %1; cvt.u32.u64 %0, t; }"
        : "=r"(s) : "l"(smem_dst));
    asm volatile("cp.async.cg.shared.global [%0], [%1], 16;" :: "r"(s), "l"(gsrc));
}
__device__ __forceinline__ void cp_commit() { asm volatile("cp.async.commit_group;"); }
template <int N>
__device__ __forceinline__ void cp_wait() { asm volatile("cp.async.wait_group %0;" :: "n"(N)); }

// m16n8k8 tf32 HMMA (pre-phase)
__device__ __forceinline__ void mma8(float* d, uint32_t a0, uint32_t a1, uint32_t a2,
                                     uint32_t a3, uint32_t b0, uint32_t b1) {
    asm volatile(
        "mma.sync.aligned.m16n8k8.row.col.f32.tf32.tf32.f32 "
        "{%0,%1,%2,%3}, {%4,%5,%6,%7}, {%8,%9}, {%0,%1,%2,%3};"
        : "+f"(d[0]), "+f"(d[1]), "+f"(d[2]), "+f"(d[3])
        : "r"(a0), "r"(a1), "r"(a2), "r"(a3), "r"(b0), "r"(b1));
}
// m16n8k16 f16 HMMA (recurrent loop)
__device__ __forceinline__ void mma16(float* d, uint32_t a0, uint32_t a1, uint32_t a2,
                                      uint32_t a3, uint32_t b0, uint32_t b1) {
    asm volatile(
        "mma.sync.aligned.m16n8k16.row.col.f32.f16.f16.f32 "
        "{%0,%1,%2,%3}, {%4,%5,%6,%7}, {%8,%9}, {%0,%1,%2,%3};"
        : "+f"(d[0]), "+f"(d[1]), "+f"(d[2]), "+f"(d[3])
        : "r"(a0), "r"(a1), "r"(a2), "r"(a3), "r"(b0), "r"(b1));
}
__device__ __forceinline__ uint32_t fb(float v) { return __float_as_uint(v); }

__device__ __forceinline__ float sigm(float x) { return 1.0f / (1.0f + __expf(-x)); }
__device__ __forceinline__ float tanh_fast(float x) {
    return 2.0f / (1.0f + __expf(-2.0f * x)) - 1.0f;
}

__device__ __forceinline__ unsigned long long ld_acq(const unsigned long long* p) {
    unsigned long long v;
    asm volatile("ld.acquire.gpu.u64 %0, [%1];" : "=l"(v) : "l"(p) : "memory");
    return v;
}
__device__ __forceinline__ void st_rel(unsigned long long* p, unsigned long long v) {
    asm volatile("st.release.gpu.u64 [%0], %1;" :: "l"(p), "l"(v) : "memory");
}

// distributed slot barrier: no same-address atomic contention.
// Each block releases its own slot; block 0's warp gathers all slots, then
// publishes g_release; others poll one address.
__device__ __forceinline__ void grid_barrier(int bid, unsigned long long tgt) {
    __syncthreads();
    if (threadIdx.x < 32) {
        if (threadIdx.x == 0) st_rel(&g_slot[bid], tgt);
        if (bid == 0) {
            const int lane = threadIdx.x;
            int ok;
            do {
                unsigned long long m0 = ld_acq(&g_slot[lane * 4 + 0]);
                unsigned long long m1 = ld_acq(&g_slot[lane * 4 + 1]);
                unsigned long long m2 = ld_acq(&g_slot[lane * 4 + 2]);
                unsigned long long m3 = ld_acq(&g_slot[lane * 4 + 3]);
                unsigned long long m = m0 < m1 ? m0 : m1;
                m = m < m2 ? m : m2;
                m = m < m3 ? m : m3;
                ok = __all_sync(0xffffffffu, m >= tgt);
            } while (!ok);
            if (lane == 0) st_rel(&g_release, tgt);
        } else if (threadIdx.x == 0) {
            while (ld_acq(&g_release) < tgt) { }
        }
    }
    __syncthreads();
}

// ---------------- kernel ----------------
__global__ void __launch_bounds__(TPB, 1)
bn_lstm_mma(const float* __restrict__ x,
            const float* __restrict__ wih,
            const float* __restrict__ whh,
            const float* __restrict__ bias,
            const float* __restrict__ gih, const float* __restrict__ bih,
            const float* __restrict__ ghh, const float* __restrict__ bhh,
            const float* __restrict__ gcc, const float* __restrict__ bcc,
            float* __restrict__ out)
{
    extern __shared__ char sm[];
    Par* P = (Par*)(sm + SM_PAR);

    const int tid  = threadIdx.x;
    const int wid  = tid >> 5;
    const int lane = tid & 31;
    const int bid  = blockIdx.x;
    const int j0   = 4 * bid;
    const int gq   = lane >> 2;       // fragment row group 0..7
    const int tq   = lane & 3;        // fragment k/col group 0..3
    const int col = tid & 63;
    const int jj  = (tid >> 6) & 3;

    // replay-safe barrier base: all slots are equal at kernel entry
    const unsigned long long bar_base = ld_acq(&g_slot[bid]);
    unsigned long long bar_t = bar_base;

    // zero h[0] (own rows), fp16 batch-major
    g_h16[0][col * HSZ + j0 + jj] = __float2half(0.0f);

    // ================= PRE-PHASE: g_bnb[t] = BN(Wih @ x_t) + bias =================
    {
        float* PW = (float*)(sm + SM_PW);
        float* PX = (float*)(sm + SM_PX);
        for (int mc = 0; mc < 16; ++mc) {
            const int rbase = mc * 128;
            __syncthreads();
            #pragma unroll
            for (int i = 0; i < 32; ++i) {
                int e = tid + i * TPB;
                int r = e >> 6, q = e & 63;
                cp_async16(&PW[r * 260 + q * 4],
                           wih + ((size_t)(rbase + r)) * 256 + q * 4);
            }
            cp_commit();

            for (int tt = 0; tt < 16; ++tt) {
                const int t = bid * 16 + tt;
                #pragma unroll
                for (int i = 0; i < 16; ++i) {
                    int e = tid + i * TPB;
                    int r = e >> 4, q = e & 15;
                    cp_async16(&PX[r * 72 + q * 4],
                               x + ((size_t)t * 256 + r) * 64 + q * 4);
                }
                cp_commit();
                cp_wait<0>();
                __syncthreads();

                float acc[8][4];
                #pragma unroll
                for (int nt = 0; nt < 8; ++nt)
                    #pragma unroll
                    for (int i = 0; i < 4; ++i) acc[nt][i] = 0.0f;

                const float* WA = PW + (wid * 16) * 260;
                #pragma unroll 4
                for (int ks = 0; ks < 32; ++ks) {
                    int k = ks * 8 + tq;
                    uint32_t a0 = fb(WA[gq * 260 + k]);
                    uint32_t a1 = fb(WA[(gq + 8) * 260 + k]);
                    uint32_t a2 = fb(WA[gq * 260 + k + 4]);
                    uint32_t a3 = fb(WA[(gq + 8) * 260 + k + 4]);
                    #pragma unroll
                    for (int nt = 0; nt < 8; ++nt) {
                        uint32_t b0 = fb(PX[k * 72 + nt * 8 + gq]);
                        uint32_t b1 = fb(PX[(k + 4) * 72 + nt * 8 + gq]);
                        mma8(acc[nt], a0, a1, a2, a3, b0, b1);
                    }
                }

                int row0 = rbase + wid * 16 + gq;
                int row1 = row0 + 8;
                float s0 = 0, q0 = 0, s1 = 0, q1 = 0;
                #pragma unroll
                for (int nt = 0; nt < 8; ++nt) {
                    s0 += acc[nt][0] + acc[nt][1];
                    q0 += acc[nt][0] * acc[nt][0] + acc[nt][1] * acc[nt][1];
                    s1 += acc[nt][2] + acc[nt][3];
                    q1 += acc[nt][2] * acc[nt][2] + acc[nt][3] * acc[nt][3];
                }
                #pragma unroll
                for (int off = 1; off < 4; off <<= 1) {
                    s0 += __shfl_xor_sync(0xffffffffu, s0, off);
                    q0 += __shfl_xor_sync(0xffffffffu, q0, off);
                    s1 += __shfl_xor_sync(0xffffffffu, s1, off);
                    q1 += __shfl_xor_sync(0xffffffffu, q1, off);
                }
                float mu0 = s0 * (1.0f / 64.0f);
                float v0  = q0 * (1.0f / 64.0f) - mu0 * mu0;
                float sc0 = rsqrtf(v0 + BN_EPS) * gih[row0];
                float sh0 = bih[row0] - mu0 * sc0 + bias[row0];
                float mu1 = s1 * (1.0f / 64.0f);
                float v1  = q1 * (1.0f / 64.0f) - mu1 * mu1;
                float sc1 = rsqrtf(v1 + BN_EPS) * gih[row1];
                float sh1 = bih[row1] - mu1 * sc1 + bias[row1];

                float* d0 = g_bnb + ((size_t)t * 2048 + row0) * 64;
                float* d1 = g_bnb + ((size_t)t * 2048 + row1) * 64;
                #pragma unroll
                for (int nt = 0; nt < 8; ++nt) {
                    *(float2*)&d0[nt * 8 + 2 * tq] =
                        make_float2(acc[nt][0] * sc0 + sh0, acc[nt][1] * sc0 + sh0);
                    *(float2*)&d1[nt * 8 + 2 * tq] =
                        make_float2(acc[nt][2] * sc1 + sh1, acc[nt][3] * sc1 + sh1);
                }
                __syncthreads();
            }
        }
    }

    grid_barrier(bid, ++bar_t);

    // ---------- recurrent-phase setup ----------
    __half*   H16  = (__half*)(sm + SM_H);
    uint32_t* H32  = (uint32_t*)(sm + SM_H);
    uint32_t* WP32 = (uint32_t*)(sm + SM_WP);
    float* SPILL   = (float*)(sm + SM_SPILL);
    float* BNB     = (float*)(sm + SM_BNB);

    if (tid < 16) {
        int grow = 512 * (tid >> 2) + j0 + (tid & 3);
        P->gh[tid] = ghh[grow]; P->bh[tid] = bhh[grow];
    }
    if (tid < 4) { P->gc[tid] = gcc[j0 + tid]; P->bc[tid] = bcc[j0 + tid]; }

    // permuted W fragments: word i -> (ks, lane, j); one LDS.128 per (ks,lane)
    for (int i = tid; i < 4096; i += TPB) {
        int ks = i >> 7, ln = (i >> 2) & 31, j = i & 3;
        int g2 = ln >> 2, t2 = ln & 3;
        int l  = g2 + 8 * (j & 1);               // local gate row 0..15
        int hc = 16 * ks + 2 * t2 + 8 * (j >> 1); // half-column (k index)
        int grow = 512 * (l >> 2) + j0 + (l & 3);
        __half2 hh = __floats2half2_rn(whh[(size_t)grow * 512 + hc],
                                       whh[(size_t)grow * 512 + hc + 1]);
        WP32[i] = *(uint32_t*)&hh;
    }
    __syncthreads();

    const int nrow260 = (wid * 8 + gq) * HSTR_W;
    const __half* hgbase0 = g_h16[0];
    const __half* hgbase1 = g_h16[1];

    // ================= recurrent loop =================
    float c_reg = 0.0f;
    for (int t = 0; t < T_STEPS; ++t) {
        const int p = t & 1;
        const __half* __restrict__ hsrc = p ? hgbase1 : hgbase0;

        // 4 chunks of h (k halves [c*128,(c+1)*128) per batch-col), block-wide coalesced
        #pragma unroll
        for (int c = 0; c < 4; ++c) {
            #pragma unroll
            for (int i = 0; i < 4; ++i) {
                int e = tid + i * TPB;          // 0..1023
                int cc = e >> 4, q = e & 15;
                cp_async16(H16 + cc * 520 + c * 128 + q * 8,
                           hsrc + cc * 512 + c * 128 + q * 8);
            }
            if (c == 3) {
                int l = tid >> 4, q = tid & 15;
                int grow = 512 * (l >> 2) + j0 + (l & 3);
                cp_async16(&BNB[l * 64 + q * 4],
                           g_bnb + ((size_t)t * 2048 + grow) * 64 + q * 4);
            }
            cp_commit();
        }

        // a = Whh @ h, pipelined over chunks; two accumulator chains
        float ac0[4] = {0, 0, 0, 0}, ac1[4] = {0, 0, 0, 0};
        #define DO_CHUNK(C)                                                     \
        {                                                                       \
            _Pragma("unroll")                                                   \
            for (int s2 = 0; s2 < 8; ++s2) {                                    \
                int ks = 8 * (C) + s2;                                          \
                uint4 aw = *(const uint4*)(WP32 + (ks * 32 + lane) * 4);        \
                uint32_t b0 = H32[nrow260 + 8 * ks + tq];                       \
                uint32_t b1 = H32[nrow260 + 8 * ks + tq + 4];                   \
                mma16((s2 & 1) ? ac1 : ac0, aw.x, aw.y, aw.z, aw.w, b0, b1);    \
            }                                                                   \
        }
        cp_wait<3>(); __syncthreads(); DO_CHUNK(0);
        cp_wait<2>(); __syncthreads(); DO_CHUNK(1);
        cp_wait<1>(); __syncthreads(); DO_CHUNK(2);
        cp_wait<0>(); __syncthreads(); DO_CHUNK(3);
        #undef DO_CHUNK

        float acc[4];
        #pragma unroll
        for (int i = 0; i < 4; ++i) acc[i] = ac0[i] + ac1[i];

        // spill D: rows {gq, gq+8}, cols wid*8 + 2tq + {0,1}
        *(float2*)&SPILL[gq * SPILL_STR + wid * 8 + 2 * tq] =
            make_float2(acc[0], acc[1]);
        *(float2*)&SPILL[(gq + 8) * SPILL_STR + wid * 8 + 2 * tq] =
            make_float2(acc[2], acc[3]);
        __syncthreads();

        // BN(a): warp w -> rows 2w, 2w+1
        {
            #pragma unroll
            for (int rr = 0; rr < 2; ++rr) {
                int r = 2 * wid + rr;
                float a0 = SPILL[r * SPILL_STR + lane];
                float a1 = SPILL[r * SPILL_STR + 32 + lane];
                float sa = a0 + a1, qa = a0 * a0 + a1 * a1;
                #pragma unroll
                for (int off = 16; off; off >>= 1) {
                    sa += __shfl_xor_sync(0xffffffffu, sa, off);
                    qa += __shfl_xor_sync(0xffffffffu, qa, off);
                }
                if (lane == 0) {
                    float mu = sa * (1.0f / 64.0f);
                    float var = qa * (1.0f / 64.0f) - mu * mu;
                    float sc = rsqrtf(var + BN_EPS) * P->gh[r];
                    P->sca[r] = sc; P->shf[r] = P->bh[r] - mu * sc;
                }
            }
        }
        __syncthreads();

        // gates + cell + BN(c) + h
        float pre[4];
        #pragma unroll
        for (int g = 0; g < 4; ++g) {
            int l = g * 4 + jj;
            pre[g] = SPILL[l * SPILL_STR + col] * P->sca[l] + P->shf[l]
                   + BNB[l * 64 + col];
        }
        float gi_ = sigm(pre[0]);
        float gf_ = sigm(pre[1]);
        float gg_ = tanh_fast(pre[2]);
        float go_ = sigm(pre[3]);
        float cn = gf_ * c_reg + gi_ * gg_;
        c_reg = cn;

        {
            float s1 = cn, s2 = cn * cn;
            #pragma unroll
            for (int off = 16; off; off >>= 1) {
                s1 += __shfl_xor_sync(0xffffffffu, s1, off);
                s2 += __shfl_xor_sync(0xffffffffu, s2, off);
            }
            if (lane == 0) { P->csum[wid] = s1; P->csq[wid] = s2; }
        }
        __syncthreads();
        // every thread computes its row's BN(c) scale from the two warp partials
        {
            float S = P->csum[2 * jj] + P->csum[2 * jj + 1];
            float Q = P->csq[2 * jj] + P->csq[2 * jj + 1];
            float mu = S * (1.0f / 64.0f);
            float var = Q * (1.0f / 64.0f) - mu * mu;
            float sc = rsqrtf(var + BN_EPS) * P->gc[jj];
            float sh = P->bc[jj] - mu * sc;
            float hv = go_ * tanh_fast(cn * sc + sh);
            g_h16[1 - p][col * HSZ + j0 + jj] = __float2half(hv);
            out[(size_t)t * (HSZ * BSZ) + (j0 + jj) * BSZ + col] = hv;
        }

        grid_barrier(bid, ++bar_t);
    }
}

// ---------------- launch ----------------
extern "C" void kernel_launch(void* const* d_in, const int* in_sizes, int n_in,
                              void* d_out, int out_size) {
    const float* x    = (const float*)d_in[0];
    const float* wih  = (const float*)d_in[1];
    const float* whh  = (const float*)d_in[2];
    const float* bias = (const float*)d_in[3];
    const float* gih  = (const float*)d_in[4];
    const float* bih  = (const float*)d_in[5];
    const float* ghh  = (const float*)d_in[6];
    const float* bhh  = (const float*)d_in[7];
    const float* gcc  = (const float*)d_in[8];
    const float* bcc  = (const float*)d_in[9];
    float* out = (float*)d_out;

    cudaFuncSetAttribute(bn_lstm_mma,
                         cudaFuncAttributeMaxDynamicSharedMemorySize, SMEM_BYTES);
    bn_lstm_mma<<<NB, TPB, SMEM_BYTES>>>(x, wih, whh, bias, gih, bih,
                                         ghh, bhh, gcc, bcc, out);
}

// round 14
// speedup vs baseline: 1.1721x; 1.1721x over previous
#include <cuda_runtime.h>
#include <cuda_fp16.h>
#include <math.h>
#include <stdint.h>

#define T_STEPS 2048
#define ISZ 256
#define HSZ 512
#define BSZ 64
#define NB 128
#define TPB 256
#define BN_EPS 1e-5f

// ---- SMEM layout (bytes) ----
// pre-phase:
#define SM_PW 0          // 128 rows x 260 floats = 133120 B
#define SM_PX 133120     // 256 rows x 72 floats  = 73728 B  -> end 206848
// recurrent phase (overlaps pre-phase region; separated by grid barrier):
#define SM_H      0      // 64 cols x 520 halves (260 words) = 66560 B
#define SM_WP     66560  // permuted W fragments: 4096 words = 16384 B -> 82944
#define SM_SPILL  82944  // 16 rows x 68 floats = 4352 B -> 87296
#define SM_BNB    87296  // 16 x 64 floats = 4096 B -> 91392
// params:
#define SM_PAR    206848
#define SMEM_BYTES 207872

#define SPILL_STR 68
#define HSTR_W 260        // H row stride in 32-bit words (520 halves)

struct Par {
    float sca[16], shf[16];
    float gh[16], bh[16];
    float gc[4], bc[4];
    float csum[8], csq[8];
};

// ---- device globals (static, no allocation) ----
__device__ __half g_h16[2][BSZ * HSZ];       // h fp16, batch-major [col][hidden]
__device__ float g_bnb[268435456];           // [t][2048 rows][64]: BN(Wih@x)+bias
__device__ unsigned long long g_arrive = 0ULL;
__device__ volatile unsigned long long g_release = 0ULL;

// ---- helpers ----
__device__ __forceinline__ void cp_async16(void* smem_dst, const void* gsrc) {
    unsigned s;
    asm("{ .reg .u64 t; cvta.to.shared.u64 t, %1; cvt.u32.u64 %0, t; }"
        : "=r"(s) : "l"(smem_dst));
    asm volatile("cp.async.cg.shared.global [%0], [%1], 16;" :: "r"(s), "l"(gsrc));
}
__device__ __forceinline__ void cp_commit() { asm volatile("cp.async.commit_group;"); }
template <int N>
__device__ __forceinline__ void cp_wait() { asm volatile("cp.async.wait_group %0;" :: "n"(N)); }

// m16n8k8 tf32 HMMA (pre-phase)
__device__ __forceinline__ void mma8(float* d, uint32_t a0, uint32_t a1, uint32_t a2,
                                     uint32_t a3, uint32_t b0, uint32_t b1) {
    asm volatile(
        "mma.sync.aligned.m16n8k8.row.col.f32.tf32.tf32.f32 "
        "{%0,%1,%2,%3}, {%4,%5,%6,%7}, {%8,%9}, {%0,%1,%2,%3};"
        : "+f"(d[0]), "+f"(d[1]), "+f"(d[2]), "+f"(d[3])
        : "r"(a0), "r"(a1), "r"(a2), "r"(a3), "r"(b0), "r"(b1));
}
// m16n8k16 f16 HMMA (recurrent loop)
__device__ __forceinline__ void mma16(float* d, uint32_t a0, uint32_t a1, uint32_t a2,
                                      uint32_t a3, uint32_t b0, uint32_t b1) {
    asm volatile(
        "mma.sync.aligned.m16n8k16.row.col.f32.f16.f16.f32 "
        "{%0,%1,%2,%3}, {%4,%5,%6,%7}, {%8,%9}, {%0,%1,%2,%3};"
        : "+f"(d[0]), "+f"(d[1]), "+f"(d[2]), "+f"(d[3])
        : "r"(a0), "r"(a1), "r"(a2), "r"(a3), "r"(b0), "r"(b1));
}
__device__ __forceinline__ uint32_t fb(float v) { return __float_as_uint(v); }

__device__ __forceinline__ float sigm(float x) { return 1.0f / (1.0f + __expf(-x)); }
__device__ __forceinline__ float tanh_fast(float x) {
    return 2.0f / (1.0f + __expf(-2.0f * x)) - 1.0f;
}

// R10 ticket barrier (best measured): threadfence + atomicAdd + volatile poll
__device__ __forceinline__ void grid_barrier() {
    __syncthreads();
    if (threadIdx.x == 0) {
        __threadfence();
        unsigned long long a = atomicAdd(&g_arrive, 1ULL);
        unsigned long long target = (a / NB + 1ULL) * NB;
        if (a % NB == NB - 1) {
            __threadfence();
            g_release = target;
        } else {
            while (g_release < target) { }
        }
    }
    __syncthreads();
}

// ---------------- kernel ----------------
__global__ void __launch_bounds__(TPB, 1)
bn_lstm_mma(const float* __restrict__ x,
            const float* __restrict__ wih,
            const float* __restrict__ whh,
            const float* __restrict__ bias,
            const float* __restrict__ gih, const float* __restrict__ bih,
            const float* __restrict__ ghh, const float* __restrict__ bhh,
            const float* __restrict__ gcc, const float* __restrict__ bcc,
            float* __restrict__ out)
{
    extern __shared__ char sm[];
    Par* P = (Par*)(sm + SM_PAR);

    const int tid  = threadIdx.x;
    const int wid  = tid >> 5;
    const int lane = tid & 31;
    const int bid  = blockIdx.x;
    const int j0   = 4 * bid;
    const int gq   = lane >> 2;       // fragment row group 0..7
    const int tq   = lane & 3;        // fragment k/col group 0..3
    const int col = tid & 63;
    const int jj  = (tid >> 6) & 3;

    // zero h[0] (own rows), fp16 batch-major
    g_h16[0][col * HSZ + j0 + jj] = __float2half(0.0f);

    // ================= PRE-PHASE: g_bnb[t] = BN(Wih @ x_t) + bias =================
    {
        float* PW = (float*)(sm + SM_PW);
        float* PX = (float*)(sm + SM_PX);
        for (int mc = 0; mc < 16; ++mc) {
            const int rbase = mc * 128;
            __syncthreads();
            #pragma unroll
            for (int i = 0; i < 32; ++i) {
                int e = tid + i * TPB;
                int r = e >> 6, q = e & 63;
                cp_async16(&PW[r * 260 + q * 4],
                           wih + ((size_t)(rbase + r)) * 256 + q * 4);
            }
            cp_commit();

            for (int tt = 0; tt < 16; ++tt) {
                const int t = bid * 16 + tt;
                #pragma unroll
                for (int i = 0; i < 16; ++i) {
                    int e = tid + i * TPB;
                    int r = e >> 4, q = e & 15;
                    cp_async16(&PX[r * 72 + q * 4],
                               x + ((size_t)t * 256 + r) * 64 + q * 4);
                }
                cp_commit();
                cp_wait<0>();
                __syncthreads();

                float acc[8][4];
                #pragma unroll
                for (int nt = 0; nt < 8; ++nt)
                    #pragma unroll
                    for (int i = 0; i < 4; ++i) acc[nt][i] = 0.0f;

                const float* WA = PW + (wid * 16) * 260;
                #pragma unroll 4
                for (int ks = 0; ks < 32; ++ks) {
                    int k = ks * 8 + tq;
                    uint32_t a0 = fb(WA[gq * 260 + k]);
                    uint32_t a1 = fb(WA[(gq + 8) * 260 + k]);
                    uint32_t a2 = fb(WA[gq * 260 + k + 4]);
                    uint32_t a3 = fb(WA[(gq + 8) * 260 + k + 4]);
                    #pragma unroll
                    for (int nt = 0; nt < 8; ++nt) {
                        uint32_t b0 = fb(PX[k * 72 + nt * 8 + gq]);
                        uint32_t b1 = fb(PX[(k + 4) * 72 + nt * 8 + gq]);
                        mma8(acc[nt], a0, a1, a2, a3, b0, b1);
                    }
                }

                int row0 = rbase + wid * 16 + gq;
                int row1 = row0 + 8;
                float s0 = 0, q0 = 0, s1 = 0, q1 = 0;
                #pragma unroll
                for (int nt = 0; nt < 8; ++nt) {
                    s0 += acc[nt][0] + acc[nt][1];
                    q0 += acc[nt][0] * acc[nt][0] + acc[nt][1] * acc[nt][1];
                    s1 += acc[nt][2] + acc[nt][3];
                    q1 += acc[nt][2] * acc[nt][2] + acc[nt][3] * acc[nt][3];
                }
                #pragma unroll
                for (int off = 1; off < 4; off <<= 1) {
                    s0 += __shfl_xor_sync(0xffffffffu, s0, off);
                    q0 += __shfl_xor_sync(0xffffffffu, q0, off);
                    s1 += __shfl_xor_sync(0xffffffffu, s1, off);
                    q1 += __shfl_xor_sync(0xffffffffu, q1, off);
                }
                float mu0 = s0 * (1.0f / 64.0f);
                float v0  = q0 * (1.0f / 64.0f) - mu0 * mu0;
                float sc0 = rsqrtf(v0 + BN_EPS) * gih[row0];
                float sh0 = bih[row0] - mu0 * sc0 + bias[row0];
                float mu1 = s1 * (1.0f / 64.0f);
                float v1  = q1 * (1.0f / 64.0f) - mu1 * mu1;
                float sc1 = rsqrtf(v1 + BN_EPS) * gih[row1];
                float sh1 = bih[row1] - mu1 * sc1 + bias[row1];

                float* d0 = g_bnb + ((size_t)t * 2048 + row0) * 64;
                float* d1 = g_bnb + ((size_t)t * 2048 + row1) * 64;
                #pragma unroll
                for (int nt = 0; nt < 8; ++nt) {
                    *(float2*)&d0[nt * 8 + 2 * tq] =
                        make_float2(acc[nt][0] * sc0 + sh0, acc[nt][1] * sc0 + sh0);
                    *(float2*)&d1[nt * 8 + 2 * tq] =
                        make_float2(acc[nt][2] * sc1 + sh1, acc[nt][3] * sc1 + sh1);
                }
                __syncthreads();
            }
        }
    }

    grid_barrier();

    // ---------- recurrent-phase setup ----------
    __half*   H16  = (__half*)(sm + SM_H);
    uint32_t* H32  = (uint32_t*)(sm + SM_H);
    uint32_t* WP32 = (uint32_t*)(sm + SM_WP);
    float* SPILL   = (float*)(sm + SM_SPILL);
    float* BNB     = (float*)(sm + SM_BNB);

    if (tid < 16) {
        int grow = 512 * (tid >> 2) + j0 + (tid & 3);
        P->gh[tid] = ghh[grow]; P->bh[tid] = bhh[grow];
    }
    if (tid < 4) { P->gc[tid] = gcc[j0 + tid]; P->bc[tid] = bcc[j0 + tid]; }

    // permuted W fragments: word i -> (ks, lane, j); one LDS.128 per (ks,lane)
    for (int i = tid; i < 4096; i += TPB) {
        int ks = i >> 7, ln = (i >> 2) & 31, j = i & 3;
        int g2 = ln >> 2, t2 = ln & 3;
        int l  = g2 + 8 * (j & 1);               // local gate row 0..15
        int hc = 16 * ks + 2 * t2 + 8 * (j >> 1); // half-column (k index)
        int grow = 512 * (l >> 2) + j0 + (l & 3);
        __half2 hh = __floats2half2_rn(whh[(size_t)grow * 512 + hc],
                                       whh[(size_t)grow * 512 + hc + 1]);
        WP32[i] = *(uint32_t*)&hh;
    }
    __syncthreads();

    const int nrow260 = (wid * 8 + gq) * HSTR_W;
    const __half* hgbase0 = g_h16[0];
    const __half* hgbase1 = g_h16[1];

    // ================= recurrent loop =================
    float c_reg = 0.0f;
    for (int t = 0; t < T_STEPS; ++t) {
        const int p = t & 1;
        const __half* __restrict__ hsrc = p ? hgbase1 : hgbase0;

        // groups 0..3: h chunks (block-wide coalesced)
        #pragma unroll
        for (int c = 0; c < 4; ++c) {
            #pragma unroll
            for (int i = 0; i < 4; ++i) {
                int e = tid + i * TPB;          // 0..1023
                int cc = e >> 4, q = e & 15;
                cp_async16(H16 + cc * 520 + c * 128 + q * 8,
                           hsrc + cc * 512 + c * 128 + q * 8);
            }
            cp_commit();
        }
        // group 4: BNB tile (DRAM-latency; only needed in epilogue)
        {
            int l = tid >> 4, q = tid & 15;
            int grow = 512 * (l >> 2) + j0 + (l & 3);
            cp_async16(&BNB[l * 64 + q * 4],
                       g_bnb + ((size_t)t * 2048 + grow) * 64 + q * 4);
        }
        cp_commit();

        // a = Whh @ h, pipelined over chunks; BNB never blocks MMA
        float ac0[4] = {0, 0, 0, 0}, ac1[4] = {0, 0, 0, 0};
        #define DO_CHUNK(C)                                                     \
        {                                                                       \
            _Pragma("unroll")                                                   \
            for (int s2 = 0; s2 < 8; ++s2) {                                    \
                int ks = 8 * (C) + s2;                                          \
                uint4 aw = *(const uint4*)(WP32 + (ks * 32 + lane) * 4);        \
                uint32_t b0 = H32[nrow260 + 8 * ks + tq];                       \
                uint32_t b1 = H32[nrow260 + 8 * ks + tq + 4];                   \
                mma16((s2 & 1) ? ac1 : ac0, aw.x, aw.y, aw.z, aw.w, b0, b1);    \
            }                                                                   \
        }
        cp_wait<4>(); __syncthreads(); DO_CHUNK(0);
        cp_wait<3>(); __syncthreads(); DO_CHUNK(1);
        cp_wait<2>(); __syncthreads(); DO_CHUNK(2);
        cp_wait<1>(); __syncthreads(); DO_CHUNK(3);
        #undef DO_CHUNK

        float acc[4];
        #pragma unroll
        for (int i = 0; i < 4; ++i) acc[i] = ac0[i] + ac1[i];

        // spill D: rows {gq, gq+8}, cols wid*8 + 2tq + {0,1}
        *(float2*)&SPILL[gq * SPILL_STR + wid * 8 + 2 * tq] =
            make_float2(acc[0], acc[1]);
        *(float2*)&SPILL[(gq + 8) * SPILL_STR + wid * 8 + 2 * tq] =
            make_float2(acc[2], acc[3]);
        __syncthreads();

        // BN(a): warp w -> rows 2w, 2w+1
        {
            #pragma unroll
            for (int rr = 0; rr < 2; ++rr) {
                int r = 2 * wid + rr;
                float a0 = SPILL[r * SPILL_STR + lane];
                float a1 = SPILL[r * SPILL_STR + 32 + lane];
                float sa = a0 + a1, qa = a0 * a0 + a1 * a1;
                #pragma unroll
                for (int off = 16; off; off >>= 1) {
                    sa += __shfl_xor_sync(0xffffffffu, sa, off);
                    qa += __shfl_xor_sync(0xffffffffu, qa, off);
                }
                if (lane == 0) {
                    float mu = sa * (1.0f / 64.0f);
                    float var = qa * (1.0f / 64.0f) - mu * mu;
                    float sc = rsqrtf(var + BN_EPS) * P->gh[r];
                    P->sca[r] = sc; P->shf[r] = P->bh[r] - mu * sc;
                }
            }
        }
        cp_wait<0>();       // BNB arrived (covered by spill+BN latency)
        __syncthreads();

        // gates + cell + BN(c) + h
        float pre[4];
        #pragma unroll
        for (int g = 0; g < 4; ++g) {
            int l = g * 4 + jj;
            pre[g] = SPILL[l * SPILL_STR + col] * P->sca[l] + P->shf[l]
                   + BNB[l * 64 + col];
        }
        float gi_ = sigm(pre[0]);
        float gf_ = sigm(pre[1]);
        float gg_ = tanh_fast(pre[2]);
        float go_ = sigm(pre[3]);
        float cn = gf_ * c_reg + gi_ * gg_;
        c_reg = cn;

        {
            float s1 = cn, s2 = cn * cn;
            #pragma unroll
            for (int off = 16; off; off >>= 1) {
                s1 += __shfl_xor_sync(0xffffffffu, s1, off);
                s2 += __shfl_xor_sync(0xffffffffu, s2, off);
            }
            if (lane == 0) { P->csum[wid] = s1; P->csq[wid] = s2; }
        }
        __syncthreads();
        // fused BN(c): every thread derives its row's scale from the warp partials
        {
            float S = P->csum[2 * jj] + P->csum[2 * jj + 1];
            float Q = P->csq[2 * jj] + P->csq[2 * jj + 1];
            float mu = S * (1.0f / 64.0f);
            float var = Q * (1.0f / 64.0f) - mu * mu;
            float sc = rsqrtf(var + BN_EPS) * P->gc[jj];
            float sh = P->bc[jj] - mu * sc;
            float hv = go_ * tanh_fast(cn * sc + sh);
            g_h16[1 - p][col * HSZ + j0 + jj] = __float2half(hv);
            out[(size_t)t * (HSZ * BSZ) + (j0 + jj) * BSZ + col] = hv;
        }

        grid_barrier();
    }
}

// ---------------- launch ----------------
extern "C" void kernel_launch(void* const* d_in, const int* in_sizes, int n_in,
                              void* d_out, int out_size) {
    const float* x    = (const float*)d_in[0];
    const float* wih  = (const float*)d_in[1];
    const float* whh  = (const float*)d_in[2];
    const float* bias = (const float*)d_in[3];
    const float* gih  = (const float*)d_in[4];
    const float* bih  = (const float*)d_in[5];
    const float* ghh  = (const float*)d_in[6];
    const float* bhh  = (const float*)d_in[7];
    const float* gcc  = (const float*)d_in[8];
    const float* bcc  = (const float*)d_in[9];
    float* out = (float*)d_out;

    cudaFuncSetAttribute(bn_lstm_mma,
                         cudaFuncAttributeMaxDynamicSharedMemorySize, SMEM_BYTES);
    bn_lstm_mma<<<NB, TPB, SMEM_BYTES>>>(x, wih, whh, bias, gih, bih,
                                         ghh, bhh, gcc, bcc, out);
}

// round 15
// speedup vs baseline: 1.2025x; 1.0260x over previous
#include <cuda_runtime.h>
#include <cuda_fp16.h>
#include <math.h>
#include <stdint.h>

#define T_STEPS 2048
#define ISZ 256
#define HSZ 512
#define BSZ 64
#define NB 128
#define TPB 256
#define BN_EPS 1e-5f

// ---- SMEM layout (bytes) ----
// pre-phase:
#define SM_PW 0          // 128 rows x 260 floats = 133120 B
#define SM_PX 133120     // 256 rows x 72 floats  = 73728 B  -> end 206848
// recurrent phase (overlaps pre-phase region; separated by grid barrier):
#define SM_H      0      // 64 cols x 520 halves (260 words) = 66560 B
#define SM_WP     66560  // permuted W fragments: 4096 words = 16384 B -> 82944
#define SM_SPILL  82944  // 16 rows x 68 floats = 4352 B -> 87296
#define SM_BNB    87296  // 2 x 16 x 64 floats = 8192 B -> 95488
#define SM_HOUT   95488  // 64 cols x 4 halves = 512 B -> 96000
// params:
#define SM_PAR    206848
#define SMEM_BYTES 207872

#define SPILL_STR 68
#define HSTR_W 260        // H row stride in 32-bit words (520 halves)

struct Par {
    float gh[16], bh[16];
    float gc[4], bc[4];
    float csum[8], csq[8];
};

// ---- device globals (static, no allocation) ----
__device__ __half g_h16[2][BSZ * HSZ];       // h fp16, batch-major [col][hidden]
__device__ float g_bnb[268435456];           // [t][2048 rows][64]: BN(Wih@x)+bias
__device__ unsigned long long g_arrive = 0ULL;
__device__ volatile unsigned long long g_release = 0ULL;

// ---- helpers ----
__device__ __forceinline__ void cp_async16(void* smem_dst, const void* gsrc) {
    unsigned s;
    asm("{ .reg .u64 t; cvta.to.shared.u64 t, %1; cvt.u32.u64 %0, t; }"
        : "=r"(s) : "l"(smem_dst));
    asm volatile("cp.async.cg.shared.global [%0], [%1], 16;" :: "r"(s), "l"(gsrc));
}
__device__ __forceinline__ void cp_commit() { asm volatile("cp.async.commit_group;"); }
template <int N>
__device__ __forceinline__ void cp_wait() { asm volatile("cp.async.wait_group %0;" :: "n"(N)); }

// m16n8k8 tf32 HMMA (pre-phase)
__device__ __forceinline__ void mma8(float* d, uint32_t a0, uint32_t a1, uint32_t a2,
                                     uint32_t a3, uint32_t b0, uint32_t b1) {
    asm volatile(
        "mma.sync.aligned.m16n8k8.row.col.f32.tf32.tf32.f32 "
        "{%0,%1,%2,%3}, {%4,%5,%6,%7}, {%8,%9}, {%0,%1,%2,%3};"
        : "+f"(d[0]), "+f"(d[1]), "+f"(d[2]), "+f"(d[3])
        : "r"(a0), "r"(a1), "r"(a2), "r"(a3), "r"(b0), "r"(b1));
}
// m16n8k16 f16 HMMA (recurrent loop)
__device__ __forceinline__ void mma16(float* d, uint32_t a0, uint32_t a1, uint32_t a2,
                                      uint32_t a3, uint32_t b0, uint32_t b1) {
    asm volatile(
        "mma.sync.aligned.m16n8k16.row.col.f32.f16.f16.f32 "
        "{%0,%1,%2,%3}, {%4,%5,%6,%7}, {%8,%9}, {%0,%1,%2,%3};"
        : "+f"(d[0]), "+f"(d[1]), "+f"(d[2]), "+f"(d[3])
        : "r"(a0), "r"(a1), "r"(a2), "r"(a3), "r"(b0), "r"(b1));
}
__device__ __forceinline__ uint32_t fb(float v) { return __float_as_uint(v); }

__device__ __forceinline__ float sigm(float x) { return 1.0f / (1.0f + __expf(-x)); }
__device__ __forceinline__ float tanh_fast(float x) {
    return 2.0f / (1.0f + __expf(-2.0f * x)) - 1.0f;
}

// R10 ticket barrier (best measured): threadfence + atomicAdd + volatile poll
__device__ __forceinline__ void grid_barrier() {
    __syncthreads();
    if (threadIdx.x == 0) {
        __threadfence();
        unsigned long long a = atomicAdd(&g_arrive, 1ULL);
        unsigned long long target = (a / NB + 1ULL) * NB;
        if (a % NB == NB - 1) {
            __threadfence();
            g_release = target;
        } else {
            while (g_release < target) { }
        }
    }
    __syncthreads();
}

// ---------------- kernel ----------------
__global__ void __launch_bounds__(TPB, 1)
bn_lstm_mma(const float* __restrict__ x,
            const float* __restrict__ wih,
            const float* __restrict__ whh,
            const float* __restrict__ bias,
            const float* __restrict__ gih, const float* __restrict__ bih,
            const float* __restrict__ ghh, const float* __restrict__ bhh,
            const float* __restrict__ gcc, const float* __restrict__ bcc,
            float* __restrict__ out)
{
    extern __shared__ char sm[];
    Par* P = (Par*)(sm + SM_PAR);

    const int tid  = threadIdx.x;
    const int wid  = tid >> 5;
    const int lane = tid & 31;
    const int bid  = blockIdx.x;
    const int j0   = 4 * bid;
    const int gq   = lane >> 2;       // fragment row group 0..7
    const int tq   = lane & 3;        // fragment k/col group 0..3
    const int col = tid & 63;
    const int jj  = (tid >> 6) & 3;

    // zero h[0] (own rows), fp16 batch-major
    g_h16[0][col * HSZ + j0 + jj] = __float2half(0.0f);

    // ================= PRE-PHASE: g_bnb[t] = BN(Wih @ x_t) + bias =================
    {
        float* PW = (float*)(sm + SM_PW);
        float* PX = (float*)(sm + SM_PX);
        for (int mc = 0; mc < 16; ++mc) {
            const int rbase = mc * 128;
            __syncthreads();
            #pragma unroll
            for (int i = 0; i < 32; ++i) {
                int e = tid + i * TPB;
                int r = e >> 6, q = e & 63;
                cp_async16(&PW[r * 260 + q * 4],
                           wih + ((size_t)(rbase + r)) * 256 + q * 4);
            }
            cp_commit();

            for (int tt = 0; tt < 16; ++tt) {
                const int t = bid * 16 + tt;
                #pragma unroll
                for (int i = 0; i < 16; ++i) {
                    int e = tid + i * TPB;
                    int r = e >> 4, q = e & 15;
                    cp_async16(&PX[r * 72 + q * 4],
                               x + ((size_t)t * 256 + r) * 64 + q * 4);
                }
                cp_commit();
                cp_wait<0>();
                __syncthreads();

                float acc[8][4];
                #pragma unroll
                for (int nt = 0; nt < 8; ++nt)
                    #pragma unroll
                    for (int i = 0; i < 4; ++i) acc[nt][i] = 0.0f;

                const float* WA = PW + (wid * 16) * 260;
                #pragma unroll 4
                for (int ks = 0; ks < 32; ++ks) {
                    int k = ks * 8 + tq;
                    uint32_t a0 = fb(WA[gq * 260 + k]);
                    uint32_t a1 = fb(WA[(gq + 8) * 260 + k]);
                    uint32_t a2 = fb(WA[gq * 260 + k + 4]);
                    uint32_t a3 = fb(WA[(gq + 8) * 260 + k + 4]);
                    #pragma unroll
                    for (int nt = 0; nt < 8; ++nt) {
                        uint32_t b0 = fb(PX[k * 72 + nt * 8 + gq]);
                        uint32_t b1 = fb(PX[(k + 4) * 72 + nt * 8 + gq]);
                        mma8(acc[nt], a0, a1, a2, a3, b0, b1);
                    }
                }

                int row0 = rbase + wid * 16 + gq;
                int row1 = row0 + 8;
                float s0 = 0, q0 = 0, s1 = 0, q1 = 0;
                #pragma unroll
                for (int nt = 0; nt < 8; ++nt) {
                    s0 += acc[nt][0] + acc[nt][1];
                    q0 += acc[nt][0] * acc[nt][0] + acc[nt][1] * acc[nt][1];
                    s1 += acc[nt][2] + acc[nt][3];
                    q1 += acc[nt][2] * acc[nt][2] + acc[nt][3] * acc[nt][3];
                }
                #pragma unroll
                for (int off = 1; off < 4; off <<= 1) {
                    s0 += __shfl_xor_sync(0xffffffffu, s0, off);
                    q0 += __shfl_xor_sync(0xffffffffu, q0, off);
                    s1 += __shfl_xor_sync(0xffffffffu, s1, off);
                    q1 += __shfl_xor_sync(0xffffffffu, q1, off);
                }
                float mu0 = s0 * (1.0f / 64.0f);
                float v0  = q0 * (1.0f / 64.0f) - mu0 * mu0;
                float sc0 = rsqrtf(v0 + BN_EPS) * gih[row0];
                float sh0 = bih[row0] - mu0 * sc0 + bias[row0];
                float mu1 = s1 * (1.0f / 64.0f);
                float v1  = q1 * (1.0f / 64.0f) - mu1 * mu1;
                float sc1 = rsqrtf(v1 + BN_EPS) * gih[row1];
                float sh1 = bih[row1] - mu1 * sc1 + bias[row1];

                float* d0 = g_bnb + ((size_t)t * 2048 + row0) * 64;
                float* d1 = g_bnb + ((size_t)t * 2048 + row1) * 64;
                #pragma unroll
                for (int nt = 0; nt < 8; ++nt) {
                    *(float2*)&d0[nt * 8 + 2 * tq] =
                        make_float2(acc[nt][0] * sc0 + sh0, acc[nt][1] * sc0 + sh0);
                    *(float2*)&d1[nt * 8 + 2 * tq] =
                        make_float2(acc[nt][2] * sc1 + sh1, acc[nt][3] * sc1 + sh1);
                }
                __syncthreads();
            }
        }
    }

    grid_barrier();

    // ---------- recurrent-phase setup ----------
    __half*   H16  = (__half*)(sm + SM_H);
    uint32_t* H32  = (uint32_t*)(sm + SM_H);
    uint32_t* WP32 = (uint32_t*)(sm + SM_WP);
    float* SPILL   = (float*)(sm + SM_SPILL);
    float* BNB     = (float*)(sm + SM_BNB);     // double buffer: [2][16*64]
    __half* HOUT   = (__half*)(sm + SM_HOUT);   // [64 cols][4 rows]

    if (tid < 16) {
        int grow = 512 * (tid >> 2) + j0 + (tid & 3);
        P->gh[tid] = ghh[grow]; P->bh[tid] = bhh[grow];
    }
    if (tid < 4) { P->gc[tid] = gcc[j0 + tid]; P->bc[tid] = bcc[j0 + tid]; }

    // permuted W fragments: word i -> (ks, lane, j); one LDS.128 per (ks,lane)
    for (int i = tid; i < 4096; i += TPB) {
        int ks = i >> 7, ln = (i >> 2) & 31, j = i & 3;
        int g2 = ln >> 2, t2 = ln & 3;
        int l  = g2 + 8 * (j & 1);               // local gate row 0..15
        int hc = 16 * ks + 2 * t2 + 8 * (j >> 1); // half-column (k index)
        int grow = 512 * (l >> 2) + j0 + (l & 3);
        __half2 hh = __floats2half2_rn(whh[(size_t)grow * 512 + hc],
                                       whh[(size_t)grow * 512 + hc + 1]);
        WP32[i] = *(uint32_t*)&hh;
    }
    __syncthreads();

    // initial BNB(0) prefetch (pre-phase data is ready after the grid barrier)
    {
        int l = tid >> 4, q = tid & 15;
        int grow = 512 * (l >> 2) + j0 + (l & 3);
        cp_async16(&BNB[l * 64 + q * 4],
                   g_bnb + ((size_t)0 * 2048 + grow) * 64 + q * 4);
        cp_commit();
    }

    // per-warp h load mapping: warp wid owns batch rows 8*wid .. 8*wid+7
    const int lrow   = 8 * wid + (lane >> 2);    // the H row this lane loads
    const int loff   = (lane & 3);               // 16B piece index within 64B
    const int nrow260 = (wid * 8 + gq) * HSTR_W;
    const __half* hgbase0 = g_h16[0];
    const __half* hgbase1 = g_h16[1];

    // ================= recurrent loop =================
    float c_reg = 0.0f;
    for (int t = 0; t < T_STEPS; ++t) {
        const int p = t & 1;
        const __half* __restrict__ hsrc = p ? hgbase1 : hgbase0;

        // per-warp: 4 chunks of own 8 rows (64B contiguous per 4 lanes)
        #pragma unroll
        for (int c = 0; c < 4; ++c) {
            #pragma unroll
            for (int i = 0; i < 4; ++i) {
                int q8 = (loff + 4 * i) * 8;     // halves offset within chunk
                cp_async16(H16 + lrow * 520 + c * 128 + q8,
                           hsrc + lrow * 512 + c * 128 + q8);
            }
            cp_commit();
        }
        // pending per warp: [BNB(t), h0, h1, h2, h3]

        // a = Whh @ h, per-warp pipeline; two accumulator chains
        float ac0[4] = {0, 0, 0, 0}, ac1[4] = {0, 0, 0, 0};
        #define DO_CHUNK(C)                                                     \
        {                                                                       \
            _Pragma("unroll")                                                   \
            for (int s2 = 0; s2 < 8; ++s2) {                                    \
                int ks = 8 * (C) + s2;                                          \
                uint4 aw = *(const uint4*)(WP32 + (ks * 32 + lane) * 4);        \
                uint32_t b0 = H32[nrow260 + 8 * ks + tq];                       \
                uint32_t b1 = H32[nrow260 + 8 * ks + tq + 4];                   \
                mma16((s2 & 1) ? ac1 : ac0, aw.x, aw.y, aw.z, aw.w, b0, b1);    \
            }                                                                   \
        }
        cp_wait<3>(); __syncwarp(); DO_CHUNK(0);
        cp_wait<2>(); __syncwarp(); DO_CHUNK(1);
        cp_wait<1>(); __syncwarp(); DO_CHUNK(2);
        cp_wait<0>(); __syncwarp(); DO_CHUNK(3);
        #undef DO_CHUNK

        float acc[4];
        #pragma unroll
        for (int i = 0; i < 4; ++i) acc[i] = ac0[i] + ac1[i];

        // spill D: rows {gq, gq+8}, cols wid*8 + 2tq + {0,1}
        *(float2*)&SPILL[gq * SPILL_STR + wid * 8 + 2 * tq] =
            make_float2(acc[0], acc[1]);
        *(float2*)&SPILL[(gq + 8) * SPILL_STR + wid * 8 + 2 * tq] =
            make_float2(acc[2], acc[3]);
        __syncthreads();

        // warp-local BN(a): each warp reduces exactly the 4 rows its epilogue needs
        float sc4[4], sh4[4];
        #pragma unroll
        for (int g = 0; g < 4; ++g) {
            int r = g * 4 + jj;
            float a0 = SPILL[r * SPILL_STR + lane];
            float a1 = SPILL[r * SPILL_STR + 32 + lane];
            float sa = a0 + a1, qa = a0 * a0 + a1 * a1;
            #pragma unroll
            for (int off = 16; off; off >>= 1) {
                sa += __shfl_xor_sync(0xffffffffu, sa, off);
                qa += __shfl_xor_sync(0xffffffffu, qa, off);
            }
            float mu = sa * (1.0f / 64.0f);
            float var = qa * (1.0f / 64.0f) - mu * mu;
            float sc = rsqrtf(var + BN_EPS) * P->gh[r];
            sc4[g] = sc; sh4[g] = P->bh[r] - mu * sc;
        }

        // gates + cell
        const float* BNBt = BNB + (t & 1) * 1024;
        float pre[4];
        #pragma unroll
        for (int g = 0; g < 4; ++g) {
            int l = g * 4 + jj;
            pre[g] = SPILL[l * SPILL_STR + col] * sc4[g] + sh4[g]
                   + BNBt[l * 64 + col];
        }
        float gi_ = sigm(pre[0]);
        float gf_ = sigm(pre[1]);
        float gg_ = tanh_fast(pre[2]);
        float go_ = sigm(pre[3]);
        float cn = gf_ * c_reg + gi_ * gg_;
        c_reg = cn;

        {
            float s1 = cn, s2 = cn * cn;
            #pragma unroll
            for (int off = 16; off; off >>= 1) {
                s1 += __shfl_xor_sync(0xffffffffu, s1, off);
                s2 += __shfl_xor_sync(0xffffffffu, s2, off);
            }
            if (lane == 0) { P->csum[wid] = s1; P->csq[wid] = s2; }
        }
        __syncthreads();
        // fused BN(c) + h
        float hv;
        {
            float S = P->csum[2 * jj] + P->csum[2 * jj + 1];
            float Q = P->csq[2 * jj] + P->csq[2 * jj + 1];
            float mu = S * (1.0f / 64.0f);
            float var = Q * (1.0f / 64.0f) - mu * mu;
            float sc = rsqrtf(var + BN_EPS) * P->gc[jj];
            float sh = P->bc[jj] - mu * sc;
            hv = go_ * tanh_fast(cn * sc + sh);
            HOUT[col * 4 + jj] = __float2half(hv);
            out[(size_t)t * (HSZ * BSZ) + (j0 + jj) * BSZ + col] = hv;
        }

        // BNB(t+1) prefetch (lands during the barrier wait)
        {
            int tn = (t + 1 < T_STEPS) ? t + 1 : t;
            int l = tid >> 4, q = tid & 15;
            int grow = 512 * (l >> 2) + j0 + (l & 3);
            cp_async16(&BNB[((t + 1) & 1) * 1024 + l * 64 + q * 4],
                       g_bnb + ((size_t)tn * 2048 + grow) * 64 + q * 4);
            cp_commit();
        }

        __syncthreads();    // HOUT staged
        // coalesced h write: 64 threads, 8B each (4 halves per batch col)
        if (tid < 64) {
            uint2 v = ((const uint2*)HOUT)[tid];
            *(uint2*)&(p ? hgbase0 : hgbase1)[tid * HSZ + j0] = v;
        }

        grid_barrier();
    }
}

// ---------------- launch ----------------
extern "C" void kernel_launch(void* const* d_in, const int* in_sizes, int n_in,
                              void* d_out, int out_size) {
    const float* x    = (const float*)d_in[0];
    const float* wih  = (const float*)d_in[1];
    const float* whh  = (const float*)d_in[2];
    const float* bias = (const float*)d_in[3];
    const float* gih  = (const float*)d_in[4];
    const float* bih  = (const float*)d_in[5];
    const float* ghh  = (const float*)d_in[6];
    const float* bhh  = (const float*)d_in[7];
    const float* gcc  = (const float*)d_in[8];
    const float* bcc  = (const float*)d_in[9];
    float* out = (float*)d_out;

    cudaFuncSetAttribute(bn_lstm_mma,
                         cudaFuncAttributeMaxDynamicSharedMemorySize, SMEM_BYTES);
    bn_lstm_mma<<<NB, TPB, SMEM_BYTES>>>(x, wih, whh, bias, gih, bih,
                                         ghh, bhh, gcc, bcc, out);
}